// round 17
// baseline (speedup 1.0000x reference)
#include <cuda_runtime.h>
#include <cuda_fp16.h>
#include <math.h>
#include <stdint.h>

// ---------------- problem constants ----------------
#define CB   2
#define CN   2048
#define CHD  2048
#define CNH  16
#define CKVH 4
#define CD   128
#define CKVD 512
#define CM   (CB*CN)     // 4096 token rows

// ---------------- scratch (device globals; no allocation allowed) ----------------
__device__ __half g_xnh[CM*CHD];     // normed tokens hi plane (fp16)
__device__ __half g_xnl[CM*CHD];     // normed tokens lo plane
__device__ __half g_wqkvh[3072*CHD]; // [Wq; Wk; Wv] hi
__device__ __half g_wqkvl[3072*CHD]; // [Wq; Wk; Wv] lo (only Q,K rows consumed)
__device__ __half g_woh[CHD*CHD];    // Wo hi only
__device__ float  g_bqkv[3072];
__device__ __half g_qh[CM*CHD];      // Q hi
__device__ __half g_ql[CM*CHD];      // Q lo
__device__ __half g_kvh[CM*1024];    // [K | V] hi
__device__ __half g_kvl[CM*1024];    // [K | V] lo (K-lo used by flash; V-lo by fixup)
__device__ __half g_ah[CM*CHD];      // attention out hi
__device__ __half g_al[CM*CHD];      // attention out lo

// ======================================================================
// helpers
// ======================================================================
__device__ __forceinline__ uint32_t smem_u32(const void* p) {
    uint32_t a;
    asm("{ .reg .u64 t; cvta.to.shared.u64 t, %1; cvt.u32.u64 %0, t; }" : "=r"(a) : "l"(p));
    return a;
}
#define CP_ASYNC16(dst, src) \
    asm volatile("cp.async.cg.shared.global [%0], [%1], 16;" :: "r"(dst), "l"(src))
#define CP_COMMIT() asm volatile("cp.async.commit_group;" ::: "memory")
#define CP_WAIT1()  asm volatile("cp.async.wait_group 1;" ::: "memory")
#define CP_WAIT0()  asm volatile("cp.async.wait_group 0;" ::: "memory")

__device__ __forceinline__ void ldm_x4(uint32_t& r0, uint32_t& r1, uint32_t& r2, uint32_t& r3,
                                       uint32_t addr) {
    asm volatile("ldmatrix.sync.aligned.m8n8.x4.shared.b16 {%0,%1,%2,%3}, [%4];"
                 : "=r"(r0), "=r"(r1), "=r"(r2), "=r"(r3) : "r"(addr));
}
__device__ __forceinline__ void ldm_x4_t(uint32_t& r0, uint32_t& r1, uint32_t& r2, uint32_t& r3,
                                         uint32_t addr) {
    asm volatile("ldmatrix.sync.aligned.m8n8.x4.trans.shared.b16 {%0,%1,%2,%3}, [%4];"
                 : "=r"(r0), "=r"(r1), "=r"(r2), "=r"(r3) : "r"(addr));
}
// fp16 MMA, fp32 accumulate
__device__ __forceinline__ void mma_f16(float c[4],
                                        uint32_t a0, uint32_t a1, uint32_t a2, uint32_t a3,
                                        uint32_t b0, uint32_t b1) {
    asm volatile("mma.sync.aligned.m16n8k16.row.col.f32.f16.f16.f32 "
                 "{%0,%1,%2,%3}, {%4,%5,%6,%7}, {%8,%9}, {%0,%1,%2,%3};"
                 : "+f"(c[0]), "+f"(c[1]), "+f"(c[2]), "+f"(c[3])
                 : "r"(a0), "r"(a1), "r"(a2), "r"(a3), "r"(b0), "r"(b1));
}
// split float pair into packed fp16 hi pair + lo pair
__device__ __forceinline__ void split2h(float x, float y, uint32_t& hi, uint32_t& lo) {
    __half2 H, L;
    H.x = __float2half(x); H.y = __float2half(y);
    L.x = __float2half(x - __half2float(H.x));
    L.y = __float2half(y - __half2float(H.y));
    hi = *reinterpret_cast<uint32_t*>(&H);
    lo = *reinterpret_cast<uint32_t*>(&L);
}
__device__ __forceinline__ uint32_t pack_h2(float x, float y) {
    __half2 H;
    H.x = __float2half(x); H.y = __float2half(y);
    return *reinterpret_cast<uint32_t*>(&H);
}

// ======================================================================
// RMSNorm fused with fp16 split emit into hi/lo planes
// ======================================================================
__global__ __launch_bounds__(256)
void rmsnorm_f16(const float* __restrict__ x, const float* __restrict__ w,
                 __half* __restrict__ yh, __half* __restrict__ yl)
{
    const int row = blockIdx.x;
    const int tid = threadIdx.x;
    const float4* xr = reinterpret_cast<const float4*>(x + (size_t)row * CHD);
    float4 v0 = xr[tid];
    float4 v1 = xr[tid + 256];
    float ss = v0.x*v0.x + v0.y*v0.y + v0.z*v0.z + v0.w*v0.w
             + v1.x*v1.x + v1.y*v1.y + v1.z*v1.z + v1.w*v1.w;
#pragma unroll
    for (int o = 16; o > 0; o >>= 1) ss += __shfl_xor_sync(0xffffffffu, ss, o);
    __shared__ float red[8];
    if ((tid & 31) == 0) red[tid >> 5] = ss;
    __syncthreads();
    float tot = red[0]+red[1]+red[2]+red[3]+red[4]+red[5]+red[6]+red[7];
    const float sc = rsqrtf(tot * (1.0f / (float)CHD) + 1.1920929e-7f);

    const float4* wr = reinterpret_cast<const float4*>(w);
    __half* yhr = yh + (size_t)row * CHD;
    __half* ylr = yl + (size_t)row * CHD;

    float4 wv[2] = { wr[tid], wr[tid + 256] };
    float4 vv[2] = { v0, v1 };
#pragma unroll
    for (int h = 0; h < 2; h++) {
        const int k = 4 * (tid + h * 256);
        float e[4] = { vv[h].x*sc*wv[h].x, vv[h].y*sc*wv[h].y,
                       vv[h].z*sc*wv[h].z, vv[h].w*sc*wv[h].w };
        uint32_t h01, l01, h23, l23;
        split2h(e[0], e[1], h01, l01);
        split2h(e[2], e[3], h23, l23);
        *reinterpret_cast<uint32_t*>(yhr + k)     = h01;
        *reinterpret_cast<uint32_t*>(yhr + k + 2) = h23;
        *reinterpret_cast<uint32_t*>(ylr + k)     = l01;
        *reinterpret_cast<uint32_t*>(ylr + k + 2) = l23;
    }
}

// ======================================================================
// weight conversion -> fp16 hi plane (+ optional lo plane)
// ======================================================================
__global__ __launch_bounds__(256)
void convert_w(const float* __restrict__ X, __half* __restrict__ Yh,
               __half* __restrict__ Yl, int total4)
{
    const int stride = gridDim.x * blockDim.x;
    for (int i = blockIdx.x * blockDim.x + threadIdx.x; i < total4; i += stride) {
        float4 v = reinterpret_cast<const float4*>(X)[i];
        const int e0 = i * 4;
        uint32_t h01, l01, h23, l23;
        split2h(v.x, v.y, h01, l01);
        split2h(v.z, v.w, h23, l23);
        *reinterpret_cast<uint32_t*>(Yh + e0)     = h01;
        *reinterpret_cast<uint32_t*>(Yh + e0 + 2) = h23;
        if (Yl) {
            *reinterpret_cast<uint32_t*>(Yl + e0)     = l01;
            *reinterpret_cast<uint32_t*>(Yl + e0 + 2) = l23;
        }
    }
}

__global__ void concat_bias3(const float* __restrict__ bq, const float* __restrict__ bk,
                             const float* __restrict__ bv, float* __restrict__ bqkv)
{
    int i = threadIdx.x + blockIdx.x * blockDim.x;
    if (i < 2048) bqkv[i] = bq[i];
    else if (i < 2560) bqkv[i] = bk[i - 2048];
    else if (i < 3072) bqkv[i] = bv[i - 2560];
}

// ======================================================================
// HMMA fp16 NT GEMM, plane split:
//   2-pass: C = Ahi*Bhi^T + Alo*Bhi^T
//   3-pass (Bl given && n0<2560): + Ahi*Blo^T  (weight residual — Q,K cols)
// 128x256 CTA tile, BK=64, 2-stage cp.async, 256 threads, warp tile 64x64.
// mode 0: fp32 out into Cf[*,2048].
// mode 1: QKV epilogue: n<2048 -> Q planes; else -> KV planes (col n-2048).
// ======================================================================
#define BM 128
#define BN 256
#define BK 64
#define KP 72
#define AT (128*KP)                   // 9216 elems
#define BT (256*KP)                   // 18432 elems
#define OFF_AH 0
#define OFF_AL AT
#define OFF_BH (2*AT)
#define OFF_BL (2*AT+BT)
#define STAGE (2*AT+2*BT)             // 55296 elems = 110592 B
#define NCHUNK (CHD / BK)             // 32
#define GSMEM_BYTES (2*STAGE*2)       // 221184

__global__ __launch_bounds__(256, 1)
void gemm_hmma(const __half* __restrict__ Ah, const __half* __restrict__ Al,
               const __half* __restrict__ Bh, const __half* __restrict__ Bl,
               const float* __restrict__ bias,
               float* __restrict__ Cf,
               __half* __restrict__ Qhp, __half* __restrict__ Qlp,
               __half* __restrict__ KVhp, __half* __restrict__ KVlp,
               int mode)
{
    extern __shared__ __half smem[];
    const uint32_t sb = smem_u32(smem);

    const int tid  = threadIdx.x;
    const int lane = tid & 31;
    const int wid  = tid >> 5;
    const int wm   = wid & 1;
    const int wn   = wid >> 1;
    const int m0 = blockIdx.y * BM;
    const int n0 = blockIdx.x * BN;

    // third pass (weight residual) only where exp() amplifies the error:
    // Q and K output columns of the QKV projection
    const bool use3 = (Bl != nullptr) && (n0 < 2560);

    const int r0 = tid >> 3;          // 0..31
    const int c0 = tid & 7;           // 16B column within 64-col k-chunk

    auto issue = [&](int kc) {
        const int st = kc & 1;
        const uint32_t bs = sb + (uint32_t)(st * STAGE) * 2;
        const size_t ko = (size_t)kc * BK + c0 * 8;
#pragma unroll
        for (int u = 0; u < 4; u++) {
            const int r = r0 + u * 32;
            const uint32_t so = (uint32_t)((r * KP + c0 * 8) * 2);
            CP_ASYNC16(bs + OFF_AH*2 + so, Ah + (size_t)(m0 + r) * CHD + ko);
            CP_ASYNC16(bs + OFF_AL*2 + so, Al + (size_t)(m0 + r) * CHD + ko);
        }
#pragma unroll
        for (int u = 0; u < 8; u++) {
            const int r = r0 + u * 32;
            const uint32_t so = (uint32_t)((r * KP + c0 * 8) * 2);
            CP_ASYNC16(bs + OFF_BH*2 + so, Bh + (size_t)(n0 + r) * CHD + ko);
        }
        if (use3) {
#pragma unroll
            for (int u = 0; u < 8; u++) {
                const int r = r0 + u * 32;
                const uint32_t so = (uint32_t)((r * KP + c0 * 8) * 2);
                CP_ASYNC16(bs + OFF_BL*2 + so, Bl + (size_t)(n0 + r) * CHD + ko);
            }
        }
        CP_COMMIT();
    };

    // fragment addressing
    const int g   = lane >> 3;
    const int grw = lane & 7;
    const int aRow = wm * 64 + (g & 1) * 8 + grw;    // + i*16
    const int aCol = (g >> 1) * 8;                   // + s*16
    const int bRow = wn * 64 + (g >> 1) * 8 + grw;   // + p*16
    const int bCol = (g & 1) * 8;                    // + s*16

    float acc[4][8][4];
#pragma unroll
    for (int i = 0; i < 4; i++)
#pragma unroll
        for (int j = 0; j < 8; j++)
#pragma unroll
            for (int t = 0; t < 4; t++) acc[i][j][t] = 0.0f;

    issue(0);

    for (int kc = 0; kc < NCHUNK; kc++) {
        if (kc + 1 < NCHUNK) { issue(kc + 1); CP_WAIT1(); }
        else { CP_WAIT0(); }
        __syncthreads();

        const int st = kc & 1;
        const uint32_t bs = sb + (uint32_t)(st * STAGE) * 2;
#pragma unroll
        for (int s = 0; s < 4; s++) {
            uint32_t ah_[4][4], al_[4][4];
#pragma unroll
            for (int i = 0; i < 4; i++) {
                const uint32_t ao = (uint32_t)(((aRow + i * 16) * KP + aCol + s * 16) * 2);
                ldm_x4(ah_[i][0], ah_[i][1], ah_[i][2], ah_[i][3], bs + OFF_AH*2 + ao);
                ldm_x4(al_[i][0], al_[i][1], al_[i][2], al_[i][3], bs + OFF_AL*2 + ao);
            }
            uint32_t bf[4][4];
#pragma unroll
            for (int p = 0; p < 4; p++) {
                const uint32_t bo = (uint32_t)(((bRow + p * 16) * KP + bCol + s * 16) * 2);
                ldm_x4(bf[p][0], bf[p][1], bf[p][2], bf[p][3], bs + OFF_BH*2 + bo);
            }
#pragma unroll
            for (int i = 0; i < 4; i++)
#pragma unroll
                for (int j = 0; j < 8; j++) {
                    const int p = j >> 1, q = (j & 1) * 2;
                    mma_f16(acc[i][j], ah_[i][0], ah_[i][1], ah_[i][2], ah_[i][3],
                            bf[p][q], bf[p][q + 1]);
                    mma_f16(acc[i][j], al_[i][0], al_[i][1], al_[i][2], al_[i][3],
                            bf[p][q], bf[p][q + 1]);
                }
            if (use3) {
#pragma unroll
                for (int p = 0; p < 4; p++) {
                    const uint32_t bo = (uint32_t)(((bRow + p * 16) * KP + bCol + s * 16) * 2);
                    ldm_x4(bf[p][0], bf[p][1], bf[p][2], bf[p][3], bs + OFF_BL*2 + bo);
                }
#pragma unroll
                for (int i = 0; i < 4; i++)
#pragma unroll
                    for (int j = 0; j < 8; j++) {
                        const int p = j >> 1, q = (j & 1) * 2;
                        mma_f16(acc[i][j], ah_[i][0], ah_[i][1], ah_[i][2], ah_[i][3],
                                bf[p][q], bf[p][q + 1]);
                    }
            }
        }
        __syncthreads();
    }

    // ---- epilogue ----
    const int rowb = m0 + wm * 64 + (lane >> 2);
    const int colb = n0 + wn * 64 + 2 * (lane & 3);
#pragma unroll
    for (int j = 0; j < 8; j++) {
        const int c = colb + j * 8;
        const float b0v = bias[c], b1v = bias[c + 1];
#pragma unroll
        for (int i = 0; i < 4; i++) {
            const int r = rowb + i * 16;
            float v0 = acc[i][j][0] + b0v, v1 = acc[i][j][1] + b1v;
            float v2 = acc[i][j][2] + b0v, v3 = acc[i][j][3] + b1v;
            if (mode == 0) {
                float2 o;
                o.x = v0; o.y = v1;
                *reinterpret_cast<float2*>(Cf + (size_t)r * CHD + c) = o;
                o.x = v2; o.y = v3;
                *reinterpret_cast<float2*>(Cf + (size_t)(r + 8) * CHD + c) = o;
            } else {
                __half *Hp, *Lp;
                size_t off1, off2;
                if (c < 2048) {
                    Hp = Qhp; Lp = Qlp;
                    off1 = (size_t)r * CHD + c;
                    off2 = (size_t)(r + 8) * CHD + c;
                } else {
                    Hp = KVhp; Lp = KVlp;
                    off1 = (size_t)r * 1024 + (c - 2048);
                    off2 = (size_t)(r + 8) * 1024 + (c - 2048);
                }
                uint32_t hi, lo;
                split2h(v0, v1, hi, lo);
                *reinterpret_cast<uint32_t*>(Hp + off1) = hi;
                *reinterpret_cast<uint32_t*>(Lp + off1) = lo;
                split2h(v2, v3, hi, lo);
                *reinterpret_cast<uint32_t*>(Hp + off2) = hi;
                *reinterpret_cast<uint32_t*>(Lp + off2) = lo;
            }
        }
    }
}

// ======================================================================
// HMMA flash attention, fp16 planes. BR=128, BC=64, D=128, 256 threads.
// QK^T: 3-pass (qh*kh + ql*kh + qh*kl). PV: 2-pass (ph*vh + pl*vh).
// Replacement mask (j<=i -> -1e9), no scaling. KV buf: kh, kl, vh planes.
// ======================================================================
#define ABR 128
#define ABC 64
#define AST 136
#define SQH 0
#define SQL (128*AST)
#define SKV0 (2*128*AST)
#define KVPL (64*AST)
#define KVBUF (3*KVPL)
#define FA_SMEM_BYTES ((SKV0 + 2*KVBUF) * 2)   // 174080

__global__ __launch_bounds__(256)
void flash_hmma(const __half* __restrict__ Qh, const __half* __restrict__ Ql,
                const __half* __restrict__ KVh, const __half* __restrict__ KVl,
                __half* __restrict__ Ahp, __half* __restrict__ Alp)
{
    const int it = blockIdx.x;
    const int h  = blockIdx.y;
    const int b  = blockIdx.z;
    const int g  = h & (CKVH - 1);
    const int i0 = it * ABR;
    const int tid = threadIdx.x;
    const int lane = tid & 31;
    const int wid = tid >> 5;

    extern __shared__ __half sm[];
    const uint32_t sb = smem_u32(sm);

    {
        const size_t qbase = (size_t)(b*CN + i0) * CHD + h*CD;
#pragma unroll
        for (int u = 0; u < 8; u++) {
            const int idx = tid + u * 256;
            const int r = idx >> 4, c8 = idx & 15;
            *reinterpret_cast<uint4*>(&sm[SQH + r*AST + c8*8]) =
                *reinterpret_cast<const uint4*>(Qh + qbase + (size_t)r*CHD + c8*8);
            *reinterpret_cast<uint4*>(&sm[SQL + r*AST + c8*8]) =
                *reinterpret_cast<const uint4*>(Ql + qbase + (size_t)r*CHD + c8*8);
        }
    }

    const int jstart = i0;
    const int ntiles = (CN - jstart) / ABC;

    auto load_kv = [&](int jc, int bf) {
        const size_t kbase = (size_t)(b*CN + jc) * 1024 + g*CD;
        const size_t vbase = kbase + 512;
        const uint32_t d0 = sb + (uint32_t)(SKV0 + bf*KVBUF) * 2;
#pragma unroll
        for (int u = 0; u < 4; u++) {
            const int idx = tid + u * 256;
            const int r = idx >> 4, c8 = idx & 15;
            const uint32_t so = (uint32_t)((r*AST + c8*8) * 2);
            const size_t go = (size_t)r * 1024 + c8*8;
            CP_ASYNC16(d0 + so,              KVh + kbase + go);   // kh
            CP_ASYNC16(d0 + KVPL*2 + so,     KVl + kbase + go);   // kl
            CP_ASYNC16(d0 + 2*KVPL*2 + so,   KVh + vbase + go);   // vh
        }
        CP_COMMIT();
    };

    load_kv(jstart, 0);

    const int gmt = lane >> 3, grw = lane & 7;
    const int aRow = wid*16 + (gmt & 1)*8 + grw;
    const int aColB = (gmt >> 1) * 8;
    const int bRowB = (gmt >> 1)*8 + grw;
    const int bColB = (gmt & 1) * 8;
    const int tRow = (gmt & 1)*8 + grw;
    const int tCol = (gmt >> 1) * 8;

    const int r1 = i0 + wid*16 + (lane >> 2);
    const int r2 = r1 + 8;

    float oa[16][4];
#pragma unroll
    for (int n = 0; n < 16; n++)
#pragma unroll
        for (int t = 0; t < 4; t++) oa[n][t] = 0.0f;
    float m1 = -INFINITY, m2 = -INFINITY, l1 = 0.0f, l2 = 0.0f;

    for (int t = 0; t < ntiles; t++) {
        const int jc = jstart + t * ABC;
        const int bf = t & 1;
        if (t + 1 < ntiles) {
            load_kv(jc + ABC, (t + 1) & 1);
            CP_WAIT1();
        } else {
            CP_WAIT0();
        }
        __syncthreads();

        const uint32_t kB = sb + (uint32_t)(SKV0 + bf*KVBUF) * 2;

        float sa[8][4];
#pragma unroll
        for (int n = 0; n < 8; n++)
#pragma unroll
            for (int q = 0; q < 4; q++) sa[n][q] = 0.0f;

#pragma unroll
        for (int s = 0; s < 8; s++) {
            uint32_t qh[4], ql[4];
            ldm_x4(qh[0], qh[1], qh[2], qh[3],
                   sb + (uint32_t)((SQH + aRow*AST + aColB + s*16) * 2));
            ldm_x4(ql[0], ql[1], ql[2], ql[3],
                   sb + (uint32_t)((SQL + aRow*AST + aColB + s*16) * 2));
#pragma unroll
            for (int nt = 0; nt < 4; nt++) {
                uint32_t kh[4], kl[4];
                const uint32_t ko = (uint32_t)(((nt*16 + bRowB)*AST + bColB + s*16) * 2);
                ldm_x4(kh[0], kh[1], kh[2], kh[3], kB + ko);
                ldm_x4(kl[0], kl[1], kl[2], kl[3], kB + KVPL*2 + ko);
                mma_f16(sa[2*nt],   qh[0], qh[1], qh[2], qh[3], kh[0], kh[1]);
                mma_f16(sa[2*nt],   ql[0], ql[1], ql[2], ql[3], kh[0], kh[1]);
                mma_f16(sa[2*nt],   qh[0], qh[1], qh[2], qh[3], kl[0], kl[1]);
                mma_f16(sa[2*nt+1], qh[0], qh[1], qh[2], qh[3], kh[2], kh[3]);
                mma_f16(sa[2*nt+1], ql[0], ql[1], ql[2], ql[3], kh[2], kh[3]);
                mma_f16(sa[2*nt+1], qh[0], qh[1], qh[2], qh[3], kl[2], kl[3]);
            }
        }

        if (jc < i0 + ABR) {
#pragma unroll
            for (int n = 0; n < 8; n++) {
                const int c0 = jc + n*8 + (lane & 3)*2;
#pragma unroll
                for (int q = 0; q < 2; q++) {
                    if (c0 + q <= r1) sa[n][q]     = -1e9f;
                    if (c0 + q <= r2) sa[n][2 + q] = -1e9f;
                }
            }
        }

        float mx1 = -INFINITY, mx2 = -INFINITY;
#pragma unroll
        for (int n = 0; n < 8; n++) {
            mx1 = fmaxf(mx1, fmaxf(sa[n][0], sa[n][1]));
            mx2 = fmaxf(mx2, fmaxf(sa[n][2], sa[n][3]));
        }
        mx1 = fmaxf(mx1, __shfl_xor_sync(0xffffffffu, mx1, 1));
        mx1 = fmaxf(mx1, __shfl_xor_sync(0xffffffffu, mx1, 2));
        mx2 = fmaxf(mx2, __shfl_xor_sync(0xffffffffu, mx2, 1));
        mx2 = fmaxf(mx2, __shfl_xor_sync(0xffffffffu, mx2, 2));
        const float mn1 = fmaxf(m1, mx1);
        const float mn2 = fmaxf(m2, mx2);
        const float al1 = __expf(m1 - mn1);
        const float al2 = __expf(m2 - mn2);
        m1 = mn1; m2 = mn2;

        float sum1 = 0.0f, sum2 = 0.0f;
#pragma unroll
        for (int n = 0; n < 8; n++) {
            sa[n][0] = __expf(sa[n][0] - mn1); sum1 += sa[n][0];
            sa[n][1] = __expf(sa[n][1] - mn1); sum1 += sa[n][1];
            sa[n][2] = __expf(sa[n][2] - mn2); sum2 += sa[n][2];
            sa[n][3] = __expf(sa[n][3] - mn2); sum2 += sa[n][3];
        }
        sum1 += __shfl_xor_sync(0xffffffffu, sum1, 1);
        sum1 += __shfl_xor_sync(0xffffffffu, sum1, 2);
        sum2 += __shfl_xor_sync(0xffffffffu, sum2, 1);
        sum2 += __shfl_xor_sync(0xffffffffu, sum2, 2);
        l1 = l1 * al1 + sum1;
        l2 = l2 * al2 + sum2;

#pragma unroll
        for (int n = 0; n < 16; n++) {
            oa[n][0] *= al1; oa[n][1] *= al1;
            oa[n][2] *= al2; oa[n][3] *= al2;
        }

        const uint32_t vhB = kB + 2*KVPL*2;
#pragma unroll
        for (int kt = 0; kt < 4; kt++) {
            uint32_t ph[4], pl[4];
            split2h(sa[2*kt][0],   sa[2*kt][1],   ph[0], pl[0]);
            split2h(sa[2*kt][2],   sa[2*kt][3],   ph[1], pl[1]);
            split2h(sa[2*kt+1][0], sa[2*kt+1][1], ph[2], pl[2]);
            split2h(sa[2*kt+1][2], sa[2*kt+1][3], ph[3], pl[3]);
#pragma unroll
            for (int nt = 0; nt < 8; nt++) {
                uint32_t vh[4];
                const uint32_t vo = (uint32_t)(((kt*16 + tRow)*AST + nt*16 + tCol) * 2);
                ldm_x4_t(vh[0], vh[1], vh[2], vh[3], vhB + vo);
                mma_f16(oa[2*nt],   ph[0], ph[1], ph[2], ph[3], vh[0], vh[1]);
                mma_f16(oa[2*nt],   pl[0], pl[1], pl[2], pl[3], vh[0], vh[1]);
                mma_f16(oa[2*nt+1], ph[0], ph[1], ph[2], ph[3], vh[2], vh[3]);
                mma_f16(oa[2*nt+1], pl[0], pl[1], pl[2], pl[3], vh[2], vh[3]);
            }
        }
        __syncthreads();
    }

    const float li1 = 1.0f / l1;
    const float li2 = 1.0f / l2;
    __half* h1p = Ahp + (size_t)(b*CN + r1) * CHD;
    __half* l1p = Alp + (size_t)(b*CN + r1) * CHD;
    __half* h2p = Ahp + (size_t)(b*CN + r2) * CHD;
    __half* l2p = Alp + (size_t)(b*CN + r2) * CHD;
#pragma unroll
    for (int n = 0; n < 16; n++) {
        const int col = h*CD + n*8 + (lane & 3)*2;
        uint32_t hi, lo;
        split2h(oa[n][0] * li1, oa[n][1] * li1, hi, lo);
        *reinterpret_cast<uint32_t*>(h1p + col) = hi;
        *reinterpret_cast<uint32_t*>(l1p + col) = lo;
        split2h(oa[n][2] * li2, oa[n][3] * li2, hi, lo);
        *reinterpret_cast<uint32_t*>(h2p + col) = hi;
        *reinterpret_cast<uint32_t*>(l2p + col) = lo;
    }
}

// ======================================================================
// Row N-1 fixup: fully-masked row -> uniform softmax -> mean(V).
// 512 threads: 4-way parallel over j per d.
// ======================================================================
__global__ __launch_bounds__(512)
void fix_last_row(const __half* __restrict__ KVh,
                  const __half* __restrict__ KVl,
                  __half* __restrict__ Ahp, __half* __restrict__ Alp)
{
    const int b = blockIdx.x;
    const int g = blockIdx.y;
    const int d = threadIdx.x & 127;
    const int part = threadIdx.x >> 7;       // 0..3
    __shared__ float acc[4][128];

    const __half* vh = KVh + (size_t)(b*CN) * 1024 + 512 + g*CD + d;
    const __half* vl = KVl + (size_t)(b*CN) * 1024 + 512 + g*CD + d;
    float s = 0.0f;
    for (int j = part * 512; j < (part + 1) * 512; j++) {
        s += __half2float(vh[(size_t)j * 1024]) + __half2float(vl[(size_t)j * 1024]);
    }
    acc[part][d] = s;
    __syncthreads();
    if (part == 0) {
        float tot = (acc[0][d] + acc[1][d] + acc[2][d] + acc[3][d]) * (1.0f / (float)CN);
        __half hi = __float2half(tot);
        __half lo = __float2half(tot - __half2float(hi));
        __half* rh = Ahp + (size_t)(b*CN + CN - 1) * CHD;
        __half* rl = Alp + (size_t)(b*CN + CN - 1) * CHD;
#pragma unroll
        for (int hh = 0; hh < 4; hh++) {
            const int h = hh * CKVH + g;
            const int col = h*CD + d;
            rh[col] = hi;
            rl[col] = lo;
        }
    }
}

// ======================================================================
// launch
// ======================================================================
extern "C" void kernel_launch(void* const* d_in, const int* in_sizes, int n_in,
                              void* d_out, int out_size)
{
    const float* tokens = (const float*)d_in[0];
    const float* norm_w = (const float*)d_in[1];
    const float* Wq = (const float*)d_in[2];
    const float* bq = (const float*)d_in[3];
    const float* Wk = (const float*)d_in[4];
    const float* bk = (const float*)d_in[5];
    const float* Wv = (const float*)d_in[6];
    const float* bv = (const float*)d_in[7];
    const float* Wo = (const float*)d_in[8];
    const float* bo = (const float*)d_in[9];
    float* out = (float*)d_out;

    __half *xnh, *xnl, *wqkvh, *wqkvl, *woh, *qh, *ql, *kvh, *kvl, *ah, *al;
    float* bqkv;
    cudaGetSymbolAddress((void**)&xnh,   g_xnh);
    cudaGetSymbolAddress((void**)&xnl,   g_xnl);
    cudaGetSymbolAddress((void**)&wqkvh, g_wqkvh);
    cudaGetSymbolAddress((void**)&wqkvl, g_wqkvl);
    cudaGetSymbolAddress((void**)&woh,   g_woh);
    cudaGetSymbolAddress((void**)&bqkv,  g_bqkv);
    cudaGetSymbolAddress((void**)&qh,    g_qh);
    cudaGetSymbolAddress((void**)&ql,    g_ql);
    cudaGetSymbolAddress((void**)&kvh,   g_kvh);
    cudaGetSymbolAddress((void**)&kvl,   g_kvl);
    cudaGetSymbolAddress((void**)&ah,    g_ah);
    cudaGetSymbolAddress((void**)&al,    g_al);

    cudaFuncSetAttribute(gemm_hmma, cudaFuncAttributeMaxDynamicSharedMemorySize, GSMEM_BYTES);
    cudaFuncSetAttribute(flash_hmma, cudaFuncAttributeMaxDynamicSharedMemorySize, FA_SMEM_BYTES);

    // 1. RMSNorm -> fp16 hi/lo planes
    rmsnorm_f16<<<CM, 256>>>(tokens, norm_w, xnh, xnl);

    // 2. weight conversions (Wq/Wk keep lo planes; Wv/Wo hi-only) + bias concat
    convert_w<<<1024, 256>>>(Wq, wqkvh, wqkvl, CHD*CHD/4);
    convert_w<<<512,  256>>>(Wk, wqkvh + (size_t)2048*CHD, wqkvl + (size_t)2048*CHD, CKVD*CHD/4);
    convert_w<<<512,  256>>>(Wv, wqkvh + (size_t)2560*CHD, nullptr, CKVD*CHD/4);
    convert_w<<<1024, 256>>>(Wo, woh, nullptr, CHD*CHD/4);
    concat_bias3<<<12, 256>>>(bq, bk, bv, bqkv);

    // 3. fused QKV projection (3-pass for Q,K cols; 2-pass for V cols)
    gemm_hmma<<<dim3(3072/BN, CM/BM), 256, GSMEM_BYTES>>>(
        xnh, xnl, wqkvh, wqkvl, bqkv, nullptr, qh, ql, kvh, kvl, 1);

    // 4. flash attention -> a hi/lo planes, then fix row N-1
    flash_hmma<<<dim3(CN/ABR, CNH, CB), 256, FA_SMEM_BYTES>>>(qh, ql, kvh, kvl, ah, al);
    fix_last_row<<<dim3(CB, CKVH), 512>>>(kvh, kvl, ah, al);

    // 5. output projection (2-pass) -> d_out (fp32)
    gemm_hmma<<<dim3(CHD/BN, CM/BM), 256, GSMEM_BYTES>>>(
        ah, al, woh, nullptr, bo, out, nullptr, nullptr, nullptr, nullptr, 0);
}